// round 9
// baseline (speedup 1.0000x reference)
#include <cuda_runtime.h>
#include <cuda_bf16.h>
#include <cstdint>
#include <math.h>

#define N2 8192
#define NHALF 4096
#define D 512
#define BM 128
#define BN 128
#define BK 32
#define NSTAGE (D / BK)        // 16
#define THREADS 256
#define NTILE 64               // N2 / BM
#define NBLK (NTILE * (NTILE + 1) / 2)   // 2080 upper-triangle tiles

__device__ float g_sq[N2];
__device__ float g_rowsum[N2];
__device__ float g_pos[N2];
__device__ __nv_bfloat16 g_fb[(size_t)N2 * D];

// ---------------- helpers ----------------
__device__ __forceinline__ uint32_t smem_u32(const void* p) {
    uint32_t a;
    asm("{ .reg .u64 t; cvta.to.shared.u64 t, %1; cvt.u32.u64 %0, t; }"
        : "=r"(a) : "l"(p));
    return a;
}
#define CP16(dst, src) \
    asm volatile("cp.async.cg.shared.global [%0], [%1], 16;" :: "r"(dst), "l"(src))
#define CP_COMMIT() asm volatile("cp.async.commit_group;" ::: "memory")
#define CP_WAIT(n)  asm volatile("cp.async.wait_group %0;" :: "n"(n) : "memory")

__device__ __forceinline__ void ldm_x4(uint32_t* r, uint32_t addr) {
    asm volatile("ldmatrix.sync.aligned.m8n8.x4.shared.b16 {%0,%1,%2,%3}, [%4];"
                 : "=r"(r[0]), "=r"(r[1]), "=r"(r[2]), "=r"(r[3]) : "r"(addr));
}
__device__ __forceinline__ void mma_bf16(float* c, const uint32_t* a, const uint32_t* b) {
    asm volatile(
        "mma.sync.aligned.m16n8k16.row.col.f32.bf16.bf16.f32 "
        "{%0,%1,%2,%3}, {%4,%5,%6,%7}, {%8,%9}, {%0,%1,%2,%3};"
        : "+f"(c[0]), "+f"(c[1]), "+f"(c[2]), "+f"(c[3])
        : "r"(a[0]), "r"(a[1]), "r"(a[2]), "r"(a[3]), "r"(b[0]), "r"(b[1]));
}

// chunk swizzle: 64B rows, 4x16B chunks; chunk c of row r stored at c ^ ((r>>1)&3)
__device__ __forceinline__ uint32_t swz(int row, int c) {
    return (uint32_t)(row * 64 + ((c ^ ((row >> 1) & 3)) << 4));
}

// -------------------------------------------------------------------------
// Kernel 1: bf16 convert + squared row norms + zero rowsums
// -------------------------------------------------------------------------
__global__ void prep_kernel(const float* __restrict__ f) {
    int row = blockIdx.x;
    int t = threadIdx.x;                       // 128
    float4 v = reinterpret_cast<const float4*>(f + (size_t)row * D)[t];
    __nv_bfloat162 p0, p1;
    p0.x = __float2bfloat16(v.x); p0.y = __float2bfloat16(v.y);
    p1.x = __float2bfloat16(v.z); p1.y = __float2bfloat16(v.w);
    __nv_bfloat162* dst = reinterpret_cast<__nv_bfloat162*>(g_fb + (size_t)row * D);
    dst[t * 2] = p0;
    dst[t * 2 + 1] = p1;
    float s = v.x * v.x + v.y * v.y + v.z * v.z + v.w * v.w;
    #pragma unroll
    for (int o = 16; o > 0; o >>= 1) s += __shfl_down_sync(0xffffffffu, s, o);
    __shared__ float ws[4];
    if ((t & 31) == 0) ws[t >> 5] = s;
    __syncthreads();
    if (t == 0) {
        g_sq[row] = ws[0] + ws[1] + ws[2] + ws[3];
        g_rowsum[row] = 0.0f;
    }
}

// -------------------------------------------------------------------------
// Kernel 2: bf16 mma.sync Gram GEMM, upper-triangle tiles only,
//           fused Cauchy epilogue; row+col partials reduced in smem
// -------------------------------------------------------------------------
__global__ __launch_bounds__(THREADS, 2)
void gram_kernel() {
    __shared__ __align__(16) char smA[2][BM * 64];   // 128 rows x 32 bf16
    __shared__ __align__(16) char smB[2][BN * 64];

    int tid = threadIdx.x;
    int wid = tid >> 5;
    int lid = tid & 31;
    int warp_m = wid & 3;           // 4 warps x 32 rows
    int warp_n = wid >> 2;          // 2 warps x 64 cols
    int tq = lid >> 2;              // 0..7
    int tr = lid & 3;               // 0..3

    // ---- decode upper-triangle tile (bm, bn), bn >= bm ----
    int t = blockIdx.x;
    int bm = (int)((129.0f - sqrtf(16641.0f - 8.0f * (float)t)) * 0.5f);
    while (64 * bm - bm * (bm - 1) / 2 > t) bm--;
    while (64 * (bm + 1) - (bm + 1) * bm / 2 <= t) bm++;
    int bn = bm + (t - (64 * bm - bm * (bm - 1) / 2));
    bool diag = (bm == bn);

    int aRow0 = bm * BM;
    int bRow0 = bn * BN;

    uint32_t sA[2] = { smem_u32(smA[0]), smem_u32(smA[1]) };
    uint32_t sB[2] = { smem_u32(smB[0]), smem_u32(smB[1]) };

    // ---- async stage loader: 128 rows x 4 chunks of 16B per tile ----
    auto issue = [&](int s) {
        int k0 = s * BK;
        #pragma unroll
        for (int h = 0; h < 2; h++) {
            int idx = tid + h * THREADS;       // 0..511
            int row = idx >> 2, c = idx & 3;
            const __nv_bfloat16* srcA = g_fb + (size_t)(aRow0 + row) * D + k0 + c * 8;
            const __nv_bfloat16* srcB = g_fb + (size_t)(bRow0 + row) * D + k0 + c * 8;
            CP16(sA[s & 1] + swz(row, c), srcA);
            CP16(sB[s & 1] + swz(row, c), srcB);
        }
        CP_COMMIT();
    };

    float acc[2][8][4];
    #pragma unroll
    for (int mi = 0; mi < 2; mi++)
        #pragma unroll
        for (int ni = 0; ni < 8; ni++)
            #pragma unroll
            for (int e = 0; e < 4; e++) acc[mi][ni][e] = 0.0f;

    issue(0);
    issue(1);

    int mat = lid >> 3, lrow = lid & 7;

    for (int s = 0; s < NSTAGE; s++) {
        if (s == NSTAGE - 1) { CP_WAIT(0); } else { CP_WAIT(1); }
        __syncthreads();
        uint32_t Ab = sA[s & 1], Bb = sB[s & 1];

        #pragma unroll
        for (int kk = 0; kk < 2; kk++) {
            uint32_t a[2][4];
            #pragma unroll
            for (int mi = 0; mi < 2; mi++) {
                int row = warp_m * 32 + mi * 16 + ((mat & 1) << 3) + lrow;
                int c = kk * 2 + (mat >> 1);
                ldm_x4(a[mi], Ab + swz(row, c));
            }
            uint32_t b[4][4];
            #pragma unroll
            for (int n2 = 0; n2 < 4; n2++) {
                int row = warp_n * 64 + n2 * 16 + ((mat >> 1) << 3) + lrow;
                int c = kk * 2 + (mat & 1);
                ldm_x4(b[n2], Bb + swz(row, c));
            }
            #pragma unroll
            for (int mi = 0; mi < 2; mi++)
                #pragma unroll
                for (int ni = 0; ni < 8; ni++)
                    mma_bf16(acc[mi][ni], a[mi], &b[ni >> 1][(ni & 1) * 2]);
        }
        __syncthreads();
        if (s + 2 < NSTAGE) issue(s + 2);
    }

    // ---------------- fused Cauchy epilogue (smem reduction board) ----------
    const float inv_t2 = 1.0f / (0.07f * 0.07f);

    // reuse dead smA as reduction board: [0:128) row partials, [128:256) cols
    float* sred = reinterpret_cast<float*>(smA);
    sred[tid] = 0.0f;
    __syncthreads();

    int jl0 = warp_n * 64 + 2 * tr;      // local col base for this thread

    #pragma unroll
    for (int mi = 0; mi < 2; mi++) {
        #pragma unroll
        for (int h = 0; h < 2; h++) {
            int il = warp_m * 32 + mi * 16 + h * 8 + tq;
            int i = aRow0 + il;
            float sqi = g_sq[i];
            int partner = i ^ NHALF;
            float rs = 0.0f;
            #pragma unroll
            for (int ni = 0; ni < 8; ni++) {
                #pragma unroll
                for (int v = 0; v < 2; v++) {
                    int jl = jl0 + ni * 8 + v;
                    int j = bRow0 + jl;
                    float dot = acc[mi][ni][h * 2 + v];
                    float d2 = fmaxf(sqi + g_sq[j] - 2.0f * dot, 0.0f);
                    float sim = __fdividef(1.0f, fmaf(d2, inv_t2, 1.0f));
                    if (j != i) rs += sim;             // diagonal cancels exactly
                    atomicAdd(&sred[128 + jl], sim);   // column partial (smem)
                    if (j == partner) {                // upper tile owns both slots
                        g_pos[i] = sim;
                        g_pos[j] = sim;                // sim[j][i] == sim[i][j]
                    }
                }
            }
            rs += __shfl_xor_sync(0xffffffffu, rs, 1);
            rs += __shfl_xor_sync(0xffffffffu, rs, 2);
            if (tr == 0) atomicAdd(&sred[il], rs);
        }
    }
    __syncthreads();

    // one global atomic per thread
    if (tid < 128) {
        atomicAdd(&g_rowsum[aRow0 + tid], sred[tid]);
    } else if (!diag) {
        // mirrored column sums; on diagonal tiles rows already counted them
        atomicAdd(&g_rowsum[bRow0 + tid - 128], sred[tid]);
    }
}

// -------------------------------------------------------------------------
// Kernel 3: loss = mean(log(rowsum) - log(pos))
// -------------------------------------------------------------------------
__global__ void finish_kernel(float* __restrict__ out) {
    int tid = threadIdx.x;   // 256
    double s = 0.0;
    for (int i = tid; i < N2; i += 256)
        s += (double)(logf(g_rowsum[i]) - logf(g_pos[i]));
    #pragma unroll
    for (int o = 16; o > 0; o >>= 1) s += __shfl_down_sync(0xffffffffu, s, o);
    __shared__ double ws[8];
    if ((tid & 31) == 0) ws[tid >> 5] = s;
    __syncthreads();
    if (tid == 0) {
        double t = 0.0;
        #pragma unroll
        for (int w = 0; w < 8; w++) t += ws[w];
        out[0] = (float)(t / (double)N2);
    }
}

// -------------------------------------------------------------------------
extern "C" void kernel_launch(void* const* d_in, const int* in_sizes, int n_in,
                              void* d_out, int out_size) {
    const float* features = (const float*)d_in[0];
    float* out = (float*)d_out;

    prep_kernel<<<N2, 128>>>(features);
    gram_kernel<<<NBLK, THREADS>>>();
    finish_kernel<<<1, 256>>>(out);
}

// round 12
// speedup vs baseline: 2.9213x; 2.9213x over previous
#include <cuda_runtime.h>
#include <cuda_bf16.h>
#include <cstdint>
#include <math.h>

#define N2 8192
#define NHALF 4096
#define D 512
#define BM 128
#define BN 128
#define BK 32
#define NSTAGE (D / BK)        // 16
#define THREADS 256
#define NTILE 64               // N2 / BM
#define NBLK (NTILE * (NTILE + 1) / 2)   // 2080 upper-triangle tiles

__device__ float g_sq[N2];
__device__ float g_rowsum[N2];
__device__ float g_pos[N2];
__device__ __nv_bfloat16 g_fb[(size_t)N2 * D];

// ---------------- helpers ----------------
__device__ __forceinline__ uint32_t smem_u32(const void* p) {
    uint32_t a;
    asm("{ .reg .u64 t; cvta.to.shared.u64 t, %1; cvt.u32.u64 %0, t; }"
        : "=r"(a) : "l"(p));
    return a;
}
#define CP16(dst, src) \
    asm volatile("cp.async.cg.shared.global [%0], [%1], 16;" :: "r"(dst), "l"(src))
#define CP_COMMIT() asm volatile("cp.async.commit_group;" ::: "memory")
#define CP_WAIT(n)  asm volatile("cp.async.wait_group %0;" :: "n"(n) : "memory")

__device__ __forceinline__ void ldm_x4(uint32_t* r, uint32_t addr) {
    asm volatile("ldmatrix.sync.aligned.m8n8.x4.shared.b16 {%0,%1,%2,%3}, [%4];"
                 : "=r"(r[0]), "=r"(r[1]), "=r"(r[2]), "=r"(r[3]) : "r"(addr));
}
__device__ __forceinline__ void mma_bf16(float* c, const uint32_t* a, const uint32_t* b) {
    asm volatile(
        "mma.sync.aligned.m16n8k16.row.col.f32.bf16.bf16.f32 "
        "{%0,%1,%2,%3}, {%4,%5,%6,%7}, {%8,%9}, {%0,%1,%2,%3};"
        : "+f"(c[0]), "+f"(c[1]), "+f"(c[2]), "+f"(c[3])
        : "r"(a[0]), "r"(a[1]), "r"(a[2]), "r"(a[3]), "r"(b[0]), "r"(b[1]));
}

// chunk swizzle: 64B rows, 4x16B chunks; chunk c of row r stored at c ^ ((r>>1)&3)
__device__ __forceinline__ uint32_t swz(int row, int c) {
    return (uint32_t)(row * 64 + ((c ^ ((row >> 1) & 3)) << 4));
}

// -------------------------------------------------------------------------
// Kernel 1: bf16 convert + squared row norms + zero rowsums
// -------------------------------------------------------------------------
__global__ void prep_kernel(const float* __restrict__ f) {
    int row = blockIdx.x;
    int t = threadIdx.x;                       // 128
    float4 v = reinterpret_cast<const float4*>(f + (size_t)row * D)[t];
    __nv_bfloat162 p0, p1;
    p0.x = __float2bfloat16(v.x); p0.y = __float2bfloat16(v.y);
    p1.x = __float2bfloat16(v.z); p1.y = __float2bfloat16(v.w);
    __nv_bfloat162* dst = reinterpret_cast<__nv_bfloat162*>(g_fb + (size_t)row * D);
    dst[t * 2] = p0;
    dst[t * 2 + 1] = p1;
    float s = v.x * v.x + v.y * v.y + v.z * v.z + v.w * v.w;
    #pragma unroll
    for (int o = 16; o > 0; o >>= 1) s += __shfl_down_sync(0xffffffffu, s, o);
    __shared__ float ws[4];
    if ((t & 31) == 0) ws[t >> 5] = s;
    __syncthreads();
    if (t == 0) {
        g_sq[row] = ws[0] + ws[1] + ws[2] + ws[3];
        g_rowsum[row] = 0.0f;
    }
}

// -------------------------------------------------------------------------
// Kernel 2: bf16 mma.sync Gram GEMM, upper-triangle tiles only,
//           register-lean column-outer Cauchy epilogue
// -------------------------------------------------------------------------
__global__ __launch_bounds__(THREADS, 2)
void gram_kernel() {
    __shared__ __align__(16) char smA[2][BM * 64];   // 128 rows x 32 bf16
    __shared__ __align__(16) char smB[2][BN * 64];

    int tid = threadIdx.x;
    int wid = tid >> 5;
    int lid = tid & 31;
    int warp_m = wid & 3;           // 4 warps x 32 rows
    int warp_n = wid >> 2;          // 2 warps x 64 cols
    int tq = lid >> 2;              // 0..7
    int tr = lid & 3;               // 0..3

    // ---- decode upper-triangle tile (bm, bn), bn >= bm ----
    int t = blockIdx.x;
    int bm = (int)((129.0f - sqrtf(16641.0f - 8.0f * (float)t)) * 0.5f);
    while (64 * bm - bm * (bm - 1) / 2 > t) bm--;
    while (64 * (bm + 1) - (bm + 1) * bm / 2 <= t) bm++;
    int bn = bm + (t - (64 * bm - bm * (bm - 1) / 2));
    bool diag = (bm == bn);

    int aRow0 = bm * BM;
    int bRow0 = bn * BN;

    uint32_t sA[2] = { smem_u32(smA[0]), smem_u32(smA[1]) };
    uint32_t sB[2] = { smem_u32(smB[0]), smem_u32(smB[1]) };

    // ---- async stage loader: 128 rows x 4 chunks of 16B per tile ----
    auto issue = [&](int s) {
        int k0 = s * BK;
        #pragma unroll
        for (int h = 0; h < 2; h++) {
            int idx = tid + h * THREADS;       // 0..511
            int row = idx >> 2, c = idx & 3;
            const __nv_bfloat16* srcA = g_fb + (size_t)(aRow0 + row) * D + k0 + c * 8;
            const __nv_bfloat16* srcB = g_fb + (size_t)(bRow0 + row) * D + k0 + c * 8;
            CP16(sA[s & 1] + swz(row, c), srcA);
            CP16(sB[s & 1] + swz(row, c), srcB);
        }
        CP_COMMIT();
    };

    float acc[2][8][4];
    #pragma unroll
    for (int mi = 0; mi < 2; mi++)
        #pragma unroll
        for (int ni = 0; ni < 8; ni++)
            #pragma unroll
            for (int e = 0; e < 4; e++) acc[mi][ni][e] = 0.0f;

    issue(0);
    issue(1);

    int mat = lid >> 3, lrow = lid & 7;

    for (int s = 0; s < NSTAGE; s++) {
        if (s == NSTAGE - 1) { CP_WAIT(0); } else { CP_WAIT(1); }
        __syncthreads();
        uint32_t Ab = sA[s & 1], Bb = sB[s & 1];

        #pragma unroll
        for (int kk = 0; kk < 2; kk++) {
            uint32_t a[2][4];
            #pragma unroll
            for (int mi = 0; mi < 2; mi++) {
                int row = warp_m * 32 + mi * 16 + ((mat & 1) << 3) + lrow;
                int c = kk * 2 + (mat >> 1);
                ldm_x4(a[mi], Ab + swz(row, c));
            }
            uint32_t b[4][4];
            #pragma unroll
            for (int n2 = 0; n2 < 4; n2++) {
                int row = warp_n * 64 + n2 * 16 + ((mat >> 1) << 3) + lrow;
                int c = kk * 2 + (mat & 1);
                ldm_x4(b[n2], Bb + swz(row, c));
            }
            #pragma unroll
            for (int mi = 0; mi < 2; mi++)
                #pragma unroll
                for (int ni = 0; ni < 8; ni++)
                    mma_bf16(acc[mi][ni], a[mi], &b[ni >> 1][(ni & 1) * 2]);
        }
        __syncthreads();
        if (s + 2 < NSTAGE) issue(s + 2);
    }

    // ------------- column-outer fused Cauchy epilogue (lean registers) ------
    const float inv_t2 = 1.0f / (0.07f * 0.07f);
    int jl0 = warp_n * 64 + 2 * tr;
    int row0 = aRow0 + warp_m * 32 + tq;     // g-th row = row0 + g*8 (g=(mi<<1)|h)

    float rs[4] = {0.0f, 0.0f, 0.0f, 0.0f};
    float sqi[4];
    #pragma unroll
    for (int g = 0; g < 4; g++) sqi[g] = g_sq[row0 + g * 8];

    #pragma unroll
    for (int ni = 0; ni < 8; ni++) {
        #pragma unroll
        for (int v = 0; v < 2; v++) {
            int j = bRow0 + jl0 + ni * 8 + v;
            float sqjv = g_sq[j];
            float cs = 0.0f;
            #pragma unroll
            for (int g = 0; g < 4; g++) {
                int mi = g >> 1, h = g & 1;    // g row offset = mi*16 + h*8 = g*8
                int i = row0 + mi * 16 + h * 8;
                float dot = acc[mi][ni][h * 2 + v];
                float d2 = fmaxf(sqi[(mi << 1) | h] + sqjv - 2.0f * dot, 0.0f);
                float sim = __fdividef(1.0f, fmaf(d2, inv_t2, 1.0f));
                if (j != i) rs[(mi << 1) | h] += sim;   // diagonal cancels exactly
                cs += sim;
                if (j == (i ^ NHALF)) {          // upper tile owns both pair slots
                    g_pos[i] = sim;
                    g_pos[j] = sim;              // sim[j][i] == sim[i][j]
                }
            }
            if (!diag) {
                // 8 lanes (tq=0..7, same tr) share this column
                cs += __shfl_xor_sync(0xffffffffu, cs, 4);
                cs += __shfl_xor_sync(0xffffffffu, cs, 8);
                cs += __shfl_xor_sync(0xffffffffu, cs, 16);
                if (tq == 0) atomicAdd(&g_rowsum[j], cs);
            }
        }
    }

    #pragma unroll
    for (int g = 0; g < 4; g++) {
        float r = rs[g];
        r += __shfl_xor_sync(0xffffffffu, r, 1);
        r += __shfl_xor_sync(0xffffffffu, r, 2);
        if (tr == 0) atomicAdd(&g_rowsum[row0 + (g >> 1) * 16 + (g & 1) * 8], r);
    }
}

// -------------------------------------------------------------------------
// Kernel 3: loss = mean(log(rowsum) - log(pos))
// -------------------------------------------------------------------------
__global__ void finish_kernel(float* __restrict__ out) {
    int tid = threadIdx.x;   // 256
    double s = 0.0;
    for (int i = tid; i < N2; i += 256)
        s += (double)(logf(g_rowsum[i]) - logf(g_pos[i]));
    #pragma unroll
    for (int o = 16; o > 0; o >>= 1) s += __shfl_down_sync(0xffffffffu, s, o);
    __shared__ double ws[8];
    if ((tid & 31) == 0) ws[tid >> 5] = s;
    __syncthreads();
    if (tid == 0) {
        double t = 0.0;
        #pragma unroll
        for (int w = 0; w < 8; w++) t += ws[w];
        out[0] = (float)(t / (double)N2);
    }
}

// -------------------------------------------------------------------------
extern "C" void kernel_launch(void* const* d_in, const int* in_sizes, int n_in,
                              void* d_out, int out_size) {
    const float* features = (const float*)d_in[0];
    float* out = (float*)d_out;

    prep_kernel<<<N2, 128>>>(features);
    gram_kernel<<<NBLK, THREADS>>>();
    finish_kernel<<<1, 256>>>(out);
}